// round 11
// baseline (speedup 1.0000x reference)
#include <cuda_runtime.h>
#include <cuda_bf16.h>
#include <cstdint>
#include <cstddef>

typedef unsigned long long u64;

// Problem shape (fixed): B=128, S=1024, D=256, H=256
#define NB 128
#define NS 1024
#define NDIM 256
#define NH 256
#define G3 768              // 3*H

// gx scratch: [b][t][gate*256+h]  (402 MB, static device allocation — allowed)
__device__ float g_gx[(size_t)NB * NS * G3];

// ---------------- f32x2 helpers (sm_103a packed fp32) ----------------
__device__ __forceinline__ u64 pk2(float x, float y) {
    u64 r; asm("mov.b64 %0, {%1, %2};" : "=l"(r) : "f"(x), "f"(y)); return r;
}
__device__ __forceinline__ float2 up2(u64 a) {
    float2 r; asm("mov.b64 {%0, %1}, %2;" : "=f"(r.x), "=f"(r.y) : "l"(a)); return r;
}
__device__ __forceinline__ u64 ffma2(u64 a, u64 b, u64 c) {
    u64 d; asm("fma.rn.f32x2 %0, %1, %2, %3;" : "=l"(d) : "l"(a), "l"(b), "l"(c)); return d;
}

__device__ __forceinline__ unsigned smem_u32(const void* p) {
    unsigned a;
    asm("{ .reg .u64 t; cvta.to.shared.u64 t, %1; cvt.u32.u64 %0, t; }" : "=r"(a) : "l"(p));
    return a;
}
__device__ __forceinline__ unsigned mapa_rank(unsigned local, int rank) {
    unsigned r;
    asm("mapa.shared::cluster.u32 %0, %1, %2;" : "=r"(r) : "r"(local), "r"(rank));
    return r;
}
__device__ __forceinline__ void st_cluster32(unsigned addr, float v) {
    asm volatile("st.shared::cluster.b32 [%0], %1;" :: "r"(addr), "f"(v) : "memory");
}
#define CLUSTER_SYNC() do { \
    asm volatile("barrier.cluster.arrive.aligned;" ::: "memory"); \
    asm volatile("barrier.cluster.wait.aligned;"   ::: "memory"); \
} while (0)

// =====================================================================
// Phase 1: g_gx[m][n] = X[m][:] @ W_ih[:, n] + b_ih[n]
//   M = 131072 (m = b*1024 + t), K = 256, N = 768 (n = gate*256 + h)
// CTA tile 128x128, 256 threads, 8x8 per thread, f32x2 FMAs, KB=16.
// =====================================================================
#define KB1 16

__global__ void __launch_bounds__(256, 2)
gru_gemm1(const float* __restrict__ X, const float* __restrict__ W,
          const float* __restrict__ bias)
{
    __shared__ float As[KB1][132];   // [k][m], padded
    __shared__ float Bs[KB1][128];   // [k][n]

    const int tid   = threadIdx.x;
    const int mBase = blockIdx.y << 7;
    const int nBase = blockIdx.x << 7;
    const int tn = tid & 15;         // n sub-tile: tn*8
    const int tm = tid >> 4;         // m sub-tile: tm*8

    // A staging: q in {tid, tid+256}; r = q>>2 (0..127), c4 = (q&3)*4 (k within chunk)
    const int ar0 = tid >> 2;
    const int ac0 = (tid & 3) << 2;
    // B staging: kr = tid>>5 (0..7, and +8), n4 = (tid&31)*4
    const int bk0 = tid >> 5;
    const int bn0 = (tid & 31) << 2;

    const float* Aptr = X + (size_t)(mBase + ar0) * NDIM + ac0;
    const float* Bptr = W + (size_t)bk0 * G3 + nBase + bn0;

    u64 acc[8][4];
#pragma unroll
    for (int i = 0; i < 8; ++i)
#pragma unroll
        for (int j = 0; j < 4; ++j) acc[i][j] = 0ull;

    float4 a0 = *(const float4*)(Aptr);
    float4 a1 = *(const float4*)(Aptr + 64 * NDIM);
    float4 b0 = *(const float4*)(Bptr);
    float4 b1 = *(const float4*)(Bptr + 8 * G3);

    for (int kc = 0; kc < NDIM; kc += KB1) {
        // stage regs -> smem
        As[ac0 + 0][ar0] = a0.x; As[ac0 + 1][ar0] = a0.y;
        As[ac0 + 2][ar0] = a0.z; As[ac0 + 3][ar0] = a0.w;
        As[ac0 + 0][ar0 + 64] = a1.x; As[ac0 + 1][ar0 + 64] = a1.y;
        As[ac0 + 2][ar0 + 64] = a1.z; As[ac0 + 3][ar0 + 64] = a1.w;
        *(float4*)&Bs[bk0][bn0]     = b0;
        *(float4*)&Bs[bk0 + 8][bn0] = b1;
        __syncthreads();

        if (kc + KB1 < NDIM) {   // prefetch next chunk
            a0 = *(const float4*)(Aptr + (kc + KB1));
            a1 = *(const float4*)(Aptr + (kc + KB1) + 64 * NDIM);
            b0 = *(const float4*)(Bptr + (size_t)(kc + KB1) * G3);
            b1 = *(const float4*)(Bptr + (size_t)(kc + KB1 + 8) * G3);
        }

#pragma unroll
        for (int kk = 0; kk < KB1; ++kk) {
            float4 aA = *(const float4*)&As[kk][tm * 8];
            float4 aB = *(const float4*)&As[kk][tm * 8 + 4];
            u64 bp0 = *(const u64*)&Bs[kk][tn * 8 + 0];
            u64 bp1 = *(const u64*)&Bs[kk][tn * 8 + 2];
            u64 bp2 = *(const u64*)&Bs[kk][tn * 8 + 4];
            u64 bp3 = *(const u64*)&Bs[kk][tn * 8 + 6];
            u64 ad[8];
            ad[0] = pk2(aA.x, aA.x); ad[1] = pk2(aA.y, aA.y);
            ad[2] = pk2(aA.z, aA.z); ad[3] = pk2(aA.w, aA.w);
            ad[4] = pk2(aB.x, aB.x); ad[5] = pk2(aB.y, aB.y);
            ad[6] = pk2(aB.z, aB.z); ad[7] = pk2(aB.w, aB.w);
#pragma unroll
            for (int i = 0; i < 8; ++i) {
                acc[i][0] = ffma2(ad[i], bp0, acc[i][0]);
                acc[i][1] = ffma2(ad[i], bp1, acc[i][1]);
                acc[i][2] = ffma2(ad[i], bp2, acc[i][2]);
                acc[i][3] = ffma2(ad[i], bp3, acc[i][3]);
            }
        }
        __syncthreads();
    }

    // epilogue: + bias, store to g_gx
    float bb[8];
#pragma unroll
    for (int j = 0; j < 8; ++j) bb[j] = __ldg(bias + nBase + tn * 8 + j);

#pragma unroll
    for (int i = 0; i < 8; ++i) {
        size_t row = (size_t)(mBase + tm * 8 + i);
        float* o = g_gx + row * G3 + nBase + tn * 8;
        float2 p0 = up2(acc[i][0]), p1 = up2(acc[i][1]);
        float2 p2 = up2(acc[i][2]), p3 = up2(acc[i][3]);
        float4 lo = make_float4(p0.x + bb[0], p0.y + bb[1], p1.x + bb[2], p1.y + bb[3]);
        float4 hi = make_float4(p2.x + bb[4], p2.y + bb[5], p3.x + bb[6], p3.y + bb[7]);
        *(float4*)(o)     = lo;
        *(float4*)(o + 4) = hi;
    }
}

// =====================================================================
// Phase 2: GRU recurrence. 16 clusters x 8 CTAs; cluster = 8 batches;
// CTA = 32 hidden columns (W_hh slice in smem). h exchanged via DSMEM.
// Smem: Ws[256][32][4] (128KB) | hbuf[2][256][8] (16KB) | part[8][8][3][32] (24KB)
// =====================================================================
#define WS_FLOATS (256 * 32 * 4)
#define HB_FLOATS (2 * 256 * 8)
#define PART_FLOATS (8 * 8 * 3 * 32)
#define SMEM2_BYTES ((WS_FLOATS + HB_FLOATS + PART_FLOATS) * 4)

__global__ void __launch_bounds__(256, 1) __cluster_dims__(8, 1, 1)
gru_rec(const float* __restrict__ mask, const float* __restrict__ Whh,
        const float* __restrict__ bhh, float* __restrict__ out)
{
    extern __shared__ float smem[];
    float* Ws   = smem;                        // [k][hc][4] : idx k*128 + hc*4 + g
    float* hbuf = smem + WS_FLOATS;            // [buf][k][lb] : buf*2048 + k*8 + lb
    float* part = smem + WS_FLOATS + HB_FLOATS;// [ks][lb][g][hc]

    const int tid  = threadIdx.x;
    const int rank = blockIdx.x & 7;           // cluster CTA rank (contiguous blocks)
    const int cid  = blockIdx.x >> 3;          // cluster id -> batches cid*8..cid*8+7
    const int hc   = tid & 31;
    const int ks   = tid >> 5;                 // compute role: k-split (warp id)
    const int lb   = tid >> 5;                 // reduce role: local batch (warp id)
    const int hcg  = rank * 32 + hc;           // global hidden column of this thread

    // ---- load W_hh slice: Ws[k][hc][g] = Whh[k][g*256 + hcg] ----
    for (int idx = tid; idx < 256 * 32 * 3; idx += 256) {
        int g  = idx >> 13;                // idx / 8192
        int r  = idx & 8191;
        int k  = r >> 5;
        int h2 = r & 31;
        Ws[k * 128 + h2 * 4 + g] = __ldg(Whh + (size_t)k * G3 + g * 256 + rank * 32 + h2);
    }
    for (int idx = tid; idx < 256 * 32; idx += 256) Ws[idx * 4 + 3] = 0.f;
    // ---- zero h buffers ----
    for (int idx = tid; idx < HB_FLOATS; idx += 256) hbuf[idx] = 0.f;

    // bias constants for reduce role
    const float bhr = __ldg(bhh + 0 * 256 + hcg);
    const float bhz = __ldg(bhh + 1 * 256 + hcg);
    const float bhn = __ldg(bhh + 2 * 256 + hcg);

    // precompute DSMEM broadcast addresses (h slot for this thread, both buffers)
    const int b_glob = cid * 8 + lb;
    unsigned la0 = smem_u32(&hbuf[0 * 2048 + hcg * 8 + lb]);
    unsigned la1 = smem_u32(&hbuf[1 * 2048 + hcg * 8 + lb]);
    unsigned ra0[8], ra1[8];
#pragma unroll
    for (int r = 0; r < 8; ++r) { ra0[r] = mapa_rank(la0, r); ra1[r] = mapa_rank(la1, r); }

    const float* wp = Ws + ks * 32 * 128 + hc * 4;   // stride 128 floats per k
    const float* hp0 = hbuf + 0 * 2048 + ks * 32 * 8;
    const float* hp1 = hbuf + 1 * 2048 + ks * 32 * 8;

    size_t gxbase = (size_t)b_glob * NS * G3 + hcg;   // + t*768, gates at +0/+256/+512
    size_t obase  = (size_t)b_glob * NS * NH + hcg;   // + t*256
    size_t mbase  = (size_t)b_glob * NS;              // + t

    __syncthreads();

    for (int t = 0; t < NS; ++t) {
        const int cur = t & 1;
        // prefetch gx + mask (consumed ~1600 cyc later)
        float gxr = __ldg(g_gx + gxbase + 0);
        float gxz = __ldg(g_gx + gxbase + 256);
        float gxn = __ldg(g_gx + gxbase + 512);
        float mv  = __ldg(mask + mbase + t);

        // ---- gh partial: 32 k x 8 batches x 3 gates per thread ----
        const float* hp = cur ? hp1 : hp0;
        u64 ar0 = 0, ar1 = 0, ar2 = 0, ar3 = 0;
        u64 az0 = 0, az1 = 0, az2 = 0, az3 = 0;
        u64 an0 = 0, an1 = 0, an2 = 0, an3 = 0;
#pragma unroll
        for (int kk = 0; kk < 32; ++kk) {
            float4 w = *(const float4*)(wp + kk * 128);
            ulonglong2 q0 = *(const ulonglong2*)(hp + kk * 8);
            ulonglong2 q1 = *(const ulonglong2*)(hp + kk * 8 + 4);
            u64 wr = pk2(w.x, w.x), wz = pk2(w.y, w.y), wn = pk2(w.z, w.z);
            ar0 = ffma2(wr, q0.x, ar0); ar1 = ffma2(wr, q0.y, ar1);
            ar2 = ffma2(wr, q1.x, ar2); ar3 = ffma2(wr, q1.y, ar3);
            az0 = ffma2(wz, q0.x, az0); az1 = ffma2(wz, q0.y, az1);
            az2 = ffma2(wz, q1.x, az2); az3 = ffma2(wz, q1.y, az3);
            an0 = ffma2(wn, q0.x, an0); an1 = ffma2(wn, q0.y, an1);
            an2 = ffma2(wn, q1.x, an2); an3 = ffma2(wn, q1.y, an3);
        }
        // write partials: part[ks][lb][g][hc]
        {
            float2 v;
            const int pb = ks * 8;
#define PW(P, G, LB0, V0, V1) \
            part[(((pb + (LB0)) * 3 + (G)) << 5) + hc] = (V0); \
            part[(((pb + (LB0) + 1) * 3 + (G)) << 5) + hc] = (V1);
            v = up2(ar0); PW(part, 0, 0, v.x, v.y)
            v = up2(ar1); PW(part, 0, 2, v.x, v.y)
            v = up2(ar2); PW(part, 0, 4, v.x, v.y)
            v = up2(ar3); PW(part, 0, 6, v.x, v.y)
            v = up2(az0); PW(part, 1, 0, v.x, v.y)
            v = up2(az1); PW(part, 1, 2, v.x, v.y)
            v = up2(az2); PW(part, 1, 4, v.x, v.y)
            v = up2(az3); PW(part, 1, 6, v.x, v.y)
            v = up2(an0); PW(part, 2, 0, v.x, v.y)
            v = up2(an1); PW(part, 2, 2, v.x, v.y)
            v = up2(an2); PW(part, 2, 4, v.x, v.y)
            v = up2(an3); PW(part, 2, 6, v.x, v.y)
#undef PW
        }
        __syncthreads();

        // ---- reduce over 8 k-splits; thread = (lb, hc) ----
        float sr = 0.f, sz = 0.f, sn = 0.f;
#pragma unroll
        for (int k2 = 0; k2 < 8; ++k2) {
            const float* pp = part + (((k2 * 8 + lb) * 3) << 5) + hc;
            sr += pp[0]; sz += pp[32]; sn += pp[64];
        }
        const float ghr = sr + bhr;
        const float ghz = sz + bhz;
        const float ghn = sn + bhn;
        const float r = 1.f / (1.f + expf(-(gxr + ghr)));
        const float z = 1.f / (1.f + expf(-(gxz + ghz)));
        const float n = tanhf(gxn + r * ghn);
        const float hprev = hbuf[cur * 2048 + hcg * 8 + lb];
        const float hnew  = (1.f - z) * n + z * hprev;
        const float ho    = mv * hnew + (1.f - mv) * hprev;

        out[obase] = ho;

        // ---- broadcast h to all 8 cluster CTAs (next buffer) ----
#pragma unroll
        for (int r2 = 0; r2 < 8; ++r2) {
            unsigned a = cur ? ra0[r2] : ra1[r2];
            st_cluster32(a, ho);
        }
        CLUSTER_SYNC();   // release DSMEM writes + step barrier

        gxbase += G3;
        obase  += NH;
    }
}

extern "C" void kernel_launch(void* const* d_in, const int* in_sizes, int n_in,
                              void* d_out, int out_size) {
    const float* x    = (const float*)d_in[0];   // [B,S,D]
    const float* mask = (const float*)d_in[1];   // [B,S]
    const float* Wih  = (const float*)d_in[2];   // [D,3H]
    const float* Whh  = (const float*)d_in[3];   // [H,3H]
    const float* bih  = (const float*)d_in[4];   // [3H]
    const float* bhh  = (const float*)d_in[5];   // [3H]
    float* out = (float*)d_out;                  // [B,S,H]

    (void)in_sizes; (void)n_in; (void)out_size;

    // Phase 1: input projection GEMM
    dim3 g1(G3 / 128, (NB * NS) / 128);          // (6, 1024)
    gru_gemm1<<<g1, 256>>>(x, Wih, bih);

    // Phase 2: clustered recurrence
    cudaFuncSetAttribute(gru_rec, cudaFuncAttributeMaxDynamicSharedMemorySize,
                         SMEM2_BYTES);
    gru_rec<<<128, 256, SMEM2_BYTES>>>(mask, Whh, bhh, out);
}

// round 12
// speedup vs baseline: 1.0432x; 1.0432x over previous
#include <cuda_runtime.h>
#include <cuda_bf16.h>
#include <cstdint>
#include <cstddef>

typedef unsigned long long u64;

// Problem shape (fixed): B=128, S=1024, D=256, H=256
#define NB 128
#define NS 1024
#define NDIM 256
#define NH 256
#define G3 768              // 3*H

// gx scratch: [b][t][gate*256+h]  (402 MB, static device allocation — allowed)
__device__ float g_gx[(size_t)NB * NS * G3];

// ---------------- f32x2 helpers (sm_103a packed fp32) ----------------
__device__ __forceinline__ u64 pk2(float x, float y) {
    u64 r; asm("mov.b64 %0, {%1, %2};" : "=l"(r) : "f"(x), "f"(y)); return r;
}
__device__ __forceinline__ float2 up2(u64 a) {
    float2 r; asm("mov.b64 {%0, %1}, %2;" : "=f"(r.x), "=f"(r.y) : "l"(a)); return r;
}
__device__ __forceinline__ u64 ffma2(u64 a, u64 b, u64 c) {
    u64 d; asm("fma.rn.f32x2 %0, %1, %2, %3;" : "=l"(d) : "l"(a), "l"(b), "l"(c)); return d;
}

__device__ __forceinline__ unsigned smem_u32(const void* p) {
    unsigned a;
    asm("{ .reg .u64 t; cvta.to.shared.u64 t, %1; cvt.u32.u64 %0, t; }" : "=r"(a) : "l"(p));
    return a;
}
__device__ __forceinline__ unsigned mapa_rank(unsigned local, int rank) {
    unsigned r;
    asm("mapa.shared::cluster.u32 %0, %1, %2;" : "=r"(r) : "r"(local), "r"(rank));
    return r;
}
#define CLUSTER_SYNC() do { \
    asm volatile("barrier.cluster.arrive.aligned;" ::: "memory"); \
    asm volatile("barrier.cluster.wait.aligned;"   ::: "memory"); \
} while (0)

__device__ __forceinline__ void mbar_init(unsigned addr, unsigned cnt) {
    asm volatile("mbarrier.init.shared.b64 [%0], %1;" :: "r"(addr), "r"(cnt) : "memory");
}
__device__ __forceinline__ void mbar_expect_tx(unsigned addr, unsigned bytes) {
    asm volatile("mbarrier.arrive.expect_tx.shared.b64 _, [%0], %1;"
                 :: "r"(addr), "r"(bytes) : "memory");
}
__device__ __forceinline__ void mbar_wait(unsigned addr, unsigned parity) {
    asm volatile(
        "{\n\t"
        ".reg .pred P;\n\t"
        "WAIT_%=:\n\t"
        "mbarrier.try_wait.parity.acquire.cta.shared::cta.b64 P, [%0], %1, 0x989680;\n\t"
        "@P bra DONE_%=;\n\t"
        "bra WAIT_%=;\n\t"
        "DONE_%=:\n\t"
        "}"
        :: "r"(addr), "r"(parity) : "memory");
}
// remote smem store that completes tx on the remote CTA's mbarrier
__device__ __forceinline__ void st_async_tx(unsigned dst, unsigned val, unsigned rbar) {
    asm volatile(
        "st.async.weak.shared::cluster.mbarrier::complete_tx::bytes.b32 [%0], %1, [%2];"
        :: "r"(dst), "r"(val), "r"(rbar) : "memory");
}

// =====================================================================
// Phase 1: g_gx[m][n] = X[m][:] @ W_ih[:, n] + b_ih[n]
//   M = 131072 (m = b*1024 + t), K = 256, N = 768 (n = gate*256 + h)
// CTA tile 128x128, 256 threads, 8x8 per thread, f32x2 FMAs, KB=16.
// =====================================================================
#define KB1 16

__global__ void __launch_bounds__(256, 2)
gru_gemm1(const float* __restrict__ X, const float* __restrict__ W,
          const float* __restrict__ bias)
{
    __shared__ float As[KB1][132];   // [k][m], padded
    __shared__ float Bs[KB1][128];   // [k][n]

    const int tid   = threadIdx.x;
    const int mBase = blockIdx.y << 7;
    const int nBase = blockIdx.x << 7;
    const int tn = tid & 15;         // n sub-tile: tn*8
    const int tm = tid >> 4;         // m sub-tile: tm*8

    const int ar0 = tid >> 2;
    const int ac0 = (tid & 3) << 2;
    const int bk0 = tid >> 5;
    const int bn0 = (tid & 31) << 2;

    const float* Aptr = X + (size_t)(mBase + ar0) * NDIM + ac0;
    const float* Bptr = W + (size_t)bk0 * G3 + nBase + bn0;

    u64 acc[8][4];
#pragma unroll
    for (int i = 0; i < 8; ++i)
#pragma unroll
        for (int j = 0; j < 4; ++j) acc[i][j] = 0ull;

    float4 a0 = *(const float4*)(Aptr);
    float4 a1 = *(const float4*)(Aptr + 64 * NDIM);
    float4 b0 = *(const float4*)(Bptr);
    float4 b1 = *(const float4*)(Bptr + 8 * G3);

    for (int kc = 0; kc < NDIM; kc += KB1) {
        As[ac0 + 0][ar0] = a0.x; As[ac0 + 1][ar0] = a0.y;
        As[ac0 + 2][ar0] = a0.z; As[ac0 + 3][ar0] = a0.w;
        As[ac0 + 0][ar0 + 64] = a1.x; As[ac0 + 1][ar0 + 64] = a1.y;
        As[ac0 + 2][ar0 + 64] = a1.z; As[ac0 + 3][ar0 + 64] = a1.w;
        *(float4*)&Bs[bk0][bn0]     = b0;
        *(float4*)&Bs[bk0 + 8][bn0] = b1;
        __syncthreads();

        if (kc + KB1 < NDIM) {
            a0 = *(const float4*)(Aptr + (kc + KB1));
            a1 = *(const float4*)(Aptr + (kc + KB1) + 64 * NDIM);
            b0 = *(const float4*)(Bptr + (size_t)(kc + KB1) * G3);
            b1 = *(const float4*)(Bptr + (size_t)(kc + KB1 + 8) * G3);
        }

#pragma unroll
        for (int kk = 0; kk < KB1; ++kk) {
            float4 aA = *(const float4*)&As[kk][tm * 8];
            float4 aB = *(const float4*)&As[kk][tm * 8 + 4];
            u64 bp0 = *(const u64*)&Bs[kk][tn * 8 + 0];
            u64 bp1 = *(const u64*)&Bs[kk][tn * 8 + 2];
            u64 bp2 = *(const u64*)&Bs[kk][tn * 8 + 4];
            u64 bp3 = *(const u64*)&Bs[kk][tn * 8 + 6];
            u64 ad[8];
            ad[0] = pk2(aA.x, aA.x); ad[1] = pk2(aA.y, aA.y);
            ad[2] = pk2(aA.z, aA.z); ad[3] = pk2(aA.w, aA.w);
            ad[4] = pk2(aB.x, aB.x); ad[5] = pk2(aB.y, aB.y);
            ad[6] = pk2(aB.z, aB.z); ad[7] = pk2(aB.w, aB.w);
#pragma unroll
            for (int i = 0; i < 8; ++i) {
                acc[i][0] = ffma2(ad[i], bp0, acc[i][0]);
                acc[i][1] = ffma2(ad[i], bp1, acc[i][1]);
                acc[i][2] = ffma2(ad[i], bp2, acc[i][2]);
                acc[i][3] = ffma2(ad[i], bp3, acc[i][3]);
            }
        }
        __syncthreads();
    }

    float bb[8];
#pragma unroll
    for (int j = 0; j < 8; ++j) bb[j] = __ldg(bias + nBase + tn * 8 + j);

#pragma unroll
    for (int i = 0; i < 8; ++i) {
        size_t row = (size_t)(mBase + tm * 8 + i);
        float* o = g_gx + row * G3 + nBase + tn * 8;
        float2 p0 = up2(acc[i][0]), p1 = up2(acc[i][1]);
        float2 p2 = up2(acc[i][2]), p3 = up2(acc[i][3]);
        float4 lo = make_float4(p0.x + bb[0], p0.y + bb[1], p1.x + bb[2], p1.y + bb[3]);
        float4 hi = make_float4(p2.x + bb[4], p2.y + bb[5], p3.x + bb[6], p3.y + bb[7]);
        *(float4*)(o)     = lo;
        *(float4*)(o + 4) = hi;
    }
}

// =====================================================================
// Phase 2: GRU recurrence. 16 clusters x 8 CTAs; cluster = 8 batches;
// CTA = 32 hidden columns. 512 threads (16-way k-split).
// Sync: double-buffered tx-mbarriers + st.async (no barrier.cluster in loop).
// Smem: Ws[256][32][4] 128KB | hbuf[2][256][8] 16KB | part[16][8][3][32] 48KB | mbar[2]
// =====================================================================
#define WS_FLOATS   (256 * 32 * 4)          // 32768
#define HB_FLOATS   (2 * 256 * 8)           // 4096
#define PART_FLOATS (16 * 8 * 3 * 32)       // 12288
#define HB_OFF_B    (WS_FLOATS * 4)                          // 131072
#define BAR_OFF_B   ((WS_FLOATS + HB_FLOATS + PART_FLOATS) * 4)  // 196608
#define SMEM2_BYTES (BAR_OFF_B + 16)
#define TX_BYTES    8192u                   // 8 CTAs x 256 floats x 4B per step

__global__ void __launch_bounds__(512, 1) __cluster_dims__(8, 1, 1)
gru_rec(const float* __restrict__ mask, const float* __restrict__ Whh,
        const float* __restrict__ bhh, float* __restrict__ out)
{
    extern __shared__ float smem[];
    float* Ws   = smem;                          // [k][hc][4]
    float* hbuf = smem + WS_FLOATS;              // [buf][k][lb]
    float* part = smem + WS_FLOATS + HB_FLOATS;  // [ks][lb][g][hc]

    const int tid  = threadIdx.x;
    const int rank = blockIdx.x & 7;
    const int cid  = blockIdx.x >> 3;
    const int hc   = tid & 31;
    const int ks   = tid >> 5;                  // 0..15 (k-split)
    const int lb   = (tid >> 5) & 7;            // reduce role (tid<256): local batch
    const int hcg  = rank * 32 + hc;

    // ---- load W_hh slice: Ws[k][hc][g] = Whh[k][g*256 + hcg] ----
    for (int idx = tid; idx < 256 * 32 * 3; idx += 512) {
        int g  = idx >> 13;
        int r  = idx & 8191;
        int k  = r >> 5;
        int h2 = r & 31;
        Ws[k * 128 + h2 * 4 + g] = __ldg(Whh + (size_t)k * G3 + g * 256 + rank * 32 + h2);
    }
    for (int idx = tid; idx < 256 * 32; idx += 512) Ws[idx * 4 + 3] = 0.f;
    for (int idx = tid; idx < HB_FLOATS; idx += 512) hbuf[idx] = 0.f;

    const unsigned smem_base = smem_u32(smem);
    const unsigned barL0 = smem_base + BAR_OFF_B;
    const unsigned barL1 = smem_base + BAR_OFF_B + 8;
    if (tid == 0) {
        mbar_init(barL0, 1);
        mbar_init(barL1, 1);
        mbar_expect_tx(barL0, TX_BYTES);
        mbar_expect_tx(barL1, TX_BYTES);
    }

    const float bhr = __ldg(bhh + 0 * 256 + hcg);
    const float bhz = __ldg(bhh + 1 * 256 + hcg);
    const float bhn = __ldg(bhh + 2 * 256 + hcg);

    // remote smem window bases for all 8 cluster ranks
    unsigned rbase[8];
#pragma unroll
    for (int r = 0; r < 8; ++r) rbase[r] = mapa_rank(smem_base, r);
    const unsigned slot_off = (unsigned)((hcg * 8 + lb) * 4);   // within hbuf[buf]

    const int b_glob = cid * 8 + lb;
    size_t gxbase = (size_t)b_glob * NS * G3 + hcg;
    size_t obase  = (size_t)b_glob * NS * NH + hcg;
    size_t mbase  = (size_t)b_glob * NS;

    const float* wp  = Ws + ks * 16 * 128 + hc * 4;   // this warp's k-range
    __syncthreads();
    CLUSTER_SYNC();   // barriers + zeroed hbuf visible cluster-wide

    unsigned p0 = 0, p1 = 0;   // per-buffer wait parity

    for (int t = 0; t < NS; ++t) {
        const int cur = t & 1;
        if (t > 0) {
            if (cur == 0) { mbar_wait(barL0, p0); p0 ^= 1; }
            else          { mbar_wait(barL1, p1); p1 ^= 1; }
            if (tid == 0 && t + 2 < NS)
                mbar_expect_tx(cur ? barL1 : barL0, TX_BYTES);
        }

        // prefetch gx + mask (consumed after the k-loop)
        float gxr = 0.f, gxz = 0.f, gxn = 0.f, mv = 0.f;
        if (tid < 256) {
            gxr = __ldg(g_gx + gxbase + 0);
            gxz = __ldg(g_gx + gxbase + 256);
            gxn = __ldg(g_gx + gxbase + 512);
            mv  = __ldg(mask + mbase + t);
        }

        // ---- gh partial: 16 k x 8 batches x 3 gates per thread ----
        const float* hp = hbuf + cur * 2048 + ks * 128;
        u64 ar0 = 0, ar1 = 0, ar2 = 0, ar3 = 0;
        u64 az0 = 0, az1 = 0, az2 = 0, az3 = 0;
        u64 an0 = 0, an1 = 0, an2 = 0, an3 = 0;
#pragma unroll
        for (int kk = 0; kk < 16; ++kk) {
            float4 w = *(const float4*)(wp + kk * 128);
            ulonglong2 q0 = *(const ulonglong2*)(hp + kk * 8);
            ulonglong2 q1 = *(const ulonglong2*)(hp + kk * 8 + 4);
            u64 wr = pk2(w.x, w.x), wz = pk2(w.y, w.y), wn = pk2(w.z, w.z);
            ar0 = ffma2(wr, q0.x, ar0); ar1 = ffma2(wr, q0.y, ar1);
            ar2 = ffma2(wr, q1.x, ar2); ar3 = ffma2(wr, q1.y, ar3);
            az0 = ffma2(wz, q0.x, az0); az1 = ffma2(wz, q0.y, az1);
            az2 = ffma2(wz, q1.x, az2); az3 = ffma2(wz, q1.y, az3);
            an0 = ffma2(wn, q0.x, an0); an1 = ffma2(wn, q0.y, an1);
            an2 = ffma2(wn, q1.x, an2); an3 = ffma2(wn, q1.y, an3);
        }
        {
            float2 v;
            const int pb = ks * 8;
#define PW(G, LB0, V0, V1) \
            part[(((pb + (LB0)) * 3 + (G)) << 5) + hc] = (V0); \
            part[(((pb + (LB0) + 1) * 3 + (G)) << 5) + hc] = (V1);
            v = up2(ar0); PW(0, 0, v.x, v.y)
            v = up2(ar1); PW(0, 2, v.x, v.y)
            v = up2(ar2); PW(0, 4, v.x, v.y)
            v = up2(ar3); PW(0, 6, v.x, v.y)
            v = up2(az0); PW(1, 0, v.x, v.y)
            v = up2(az1); PW(1, 2, v.x, v.y)
            v = up2(az2); PW(1, 4, v.x, v.y)
            v = up2(az3); PW(1, 6, v.x, v.y)
            v = up2(an0); PW(2, 0, v.x, v.y)
            v = up2(an1); PW(2, 2, v.x, v.y)
            v = up2(an2); PW(2, 4, v.x, v.y)
            v = up2(an3); PW(2, 6, v.x, v.y)
#undef PW
        }
        __syncthreads();

        // ---- warps 0-7: reduce over 16 k-splits, gates, output, broadcast ----
        if (tid < 256) {
            float sr = 0.f, sz = 0.f, sn = 0.f;
#pragma unroll
            for (int k2 = 0; k2 < 16; ++k2) {
                const float* pp = part + (((k2 * 8 + lb) * 3) << 5) + hc;
                sr += pp[0]; sz += pp[32]; sn += pp[64];
            }
            const float ghr = sr + bhr;
            const float ghz = sz + bhz;
            const float ghn = sn + bhn;
            const float r = 1.f / (1.f + expf(-(gxr + ghr)));
            const float z = 1.f / (1.f + expf(-(gxz + ghz)));
            const float n = tanhf(gxn + r * ghn);
            const float hprev = hbuf[cur * 2048 + hcg * 8 + lb];
            const float hnew  = (1.f - z) * n + z * hprev;
            const float ho    = mv * hnew + (1.f - mv) * hprev;

            out[obase] = ho;

            if (t + 1 < NS) {
                const int nxt = cur ^ 1;
                const unsigned c_data = HB_OFF_B + (unsigned)nxt * 8192u + slot_off;
                const unsigned c_bar  = BAR_OFF_B + (unsigned)nxt * 8u;
                const unsigned hv = __float_as_uint(ho);
#pragma unroll
                for (int r2 = 0; r2 < 8; ++r2)
                    st_async_tx(rbase[r2] + c_data, hv, rbase[r2] + c_bar);
            }
        }

        gxbase += G3;
        obase  += NH;
    }
}

extern "C" void kernel_launch(void* const* d_in, const int* in_sizes, int n_in,
                              void* d_out, int out_size) {
    const float* x    = (const float*)d_in[0];   // [B,S,D]
    const float* mask = (const float*)d_in[1];   // [B,S]
    const float* Wih  = (const float*)d_in[2];   // [D,3H]
    const float* Whh  = (const float*)d_in[3];   // [H,3H]
    const float* bih  = (const float*)d_in[4];   // [3H]
    const float* bhh  = (const float*)d_in[5];   // [3H]
    float* out = (float*)d_out;                  // [B,S,H]

    (void)in_sizes; (void)n_in; (void)out_size;

    // Phase 1: input projection GEMM
    dim3 g1(G3 / 128, (NB * NS) / 128);          // (6, 1024)
    gru_gemm1<<<g1, 256>>>(x, Wih, bih);

    // Phase 2: clustered recurrence
    cudaFuncSetAttribute(gru_rec, cudaFuncAttributeMaxDynamicSharedMemorySize,
                         SMEM2_BYTES);
    gru_rec<<<128, 512, SMEM2_BYTES>>>(mask, Whh, bhh, out);
}

// round 13
// speedup vs baseline: 1.7067x; 1.6360x over previous
#include <cuda_runtime.h>
#include <cuda_bf16.h>
#include <cstdint>
#include <cstddef>

typedef unsigned long long u64;

// Problem shape (fixed): B=128, S=1024, D=256, H=256
#define NB 128
#define NS 1024
#define NDIM 256
#define NH 256
#define G3 768              // 3*H

// gx scratch: [b][t][gate*256+h]  (402 MB, static device allocation — allowed)
__device__ float g_gx[(size_t)NB * NS * G3];

// ---------------- f32x2 helpers (sm_103a packed fp32) ----------------
__device__ __forceinline__ u64 pk2(float x, float y) {
    u64 r; asm("mov.b64 %0, {%1, %2};" : "=l"(r) : "f"(x), "f"(y)); return r;
}
__device__ __forceinline__ float2 up2(u64 a) {
    float2 r; asm("mov.b64 {%0, %1}, %2;" : "=f"(r.x), "=f"(r.y) : "l"(a)); return r;
}
__device__ __forceinline__ u64 ffma2(u64 a, u64 b, u64 c) {
    u64 d; asm("fma.rn.f32x2 %0, %1, %2, %3;" : "=l"(d) : "l"(a), "l"(b), "l"(c)); return d;
}
__device__ __forceinline__ float tanh_fast(float x) {
    float r; asm("tanh.approx.f32 %0, %1;" : "=f"(r) : "f"(x)); return r;
}
__device__ __forceinline__ float sigm_fast(float x) {
    // sigmoid(x) = 0.5 * tanh(x/2) + 0.5
    return fmaf(0.5f, tanh_fast(0.5f * x), 0.5f);
}

__device__ __forceinline__ unsigned smem_u32(const void* p) {
    unsigned a;
    asm("{ .reg .u64 t; cvta.to.shared.u64 t, %1; cvt.u32.u64 %0, t; }" : "=r"(a) : "l"(p));
    return a;
}
__device__ __forceinline__ unsigned mapa_rank(unsigned local, int rank) {
    unsigned r;
    asm("mapa.shared::cluster.u32 %0, %1, %2;" : "=r"(r) : "r"(local), "r"(rank));
    return r;
}
#define CLUSTER_SYNC() do { \
    asm volatile("barrier.cluster.arrive.aligned;" ::: "memory"); \
    asm volatile("barrier.cluster.wait.aligned;"   ::: "memory"); \
} while (0)

__device__ __forceinline__ void mbar_init(unsigned addr, unsigned cnt) {
    asm volatile("mbarrier.init.shared.b64 [%0], %1;" :: "r"(addr), "r"(cnt) : "memory");
}
__device__ __forceinline__ void mbar_expect_tx(unsigned addr, unsigned bytes) {
    asm volatile("mbarrier.arrive.expect_tx.shared.b64 _, [%0], %1;"
                 :: "r"(addr), "r"(bytes) : "memory");
}
__device__ __forceinline__ void mbar_wait(unsigned addr, unsigned parity) {
    asm volatile(
        "{\n\t"
        ".reg .pred P;\n\t"
        "WAIT_%=:\n\t"
        "mbarrier.try_wait.parity.acquire.cta.shared::cta.b64 P, [%0], %1, 0x989680;\n\t"
        "@P bra DONE_%=;\n\t"
        "bra WAIT_%=;\n\t"
        "DONE_%=:\n\t"
        "}"
        :: "r"(addr), "r"(parity) : "memory");
}
// remote smem store that completes tx on the remote CTA's mbarrier
__device__ __forceinline__ void st_async_tx(unsigned dst, unsigned val, unsigned rbar) {
    asm volatile(
        "st.async.weak.shared::cluster.mbarrier::complete_tx::bytes.b32 [%0], %1, [%2];"
        :: "r"(dst), "r"(val), "r"(rbar) : "memory");
}

// =====================================================================
// Phase 1: g_gx[m][n] = X[m][:] @ W_ih[:, n] + b_ih[n]
//   M = 131072 (m = b*1024 + t), K = 256, N = 768 (n = gate*256 + h)
// CTA tile 128x128, 256 threads, 8x8 per thread, f32x2 FMAs, KB=16.
// =====================================================================
#define KB1 16

__global__ void __launch_bounds__(256, 2)
gru_gemm1(const float* __restrict__ X, const float* __restrict__ W,
          const float* __restrict__ bias)
{
    __shared__ float As[KB1][132];   // [k][m], padded
    __shared__ float Bs[KB1][128];   // [k][n]

    const int tid   = threadIdx.x;
    const int mBase = blockIdx.y << 7;
    const int nBase = blockIdx.x << 7;
    const int tn = tid & 15;         // n sub-tile: tn*8
    const int tm = tid >> 4;         // m sub-tile: tm*8

    const int ar0 = tid >> 2;
    const int ac0 = (tid & 3) << 2;
    const int bk0 = tid >> 5;
    const int bn0 = (tid & 31) << 2;

    const float* Aptr = X + (size_t)(mBase + ar0) * NDIM + ac0;
    const float* Bptr = W + (size_t)bk0 * G3 + nBase + bn0;

    u64 acc[8][4];
#pragma unroll
    for (int i = 0; i < 8; ++i)
#pragma unroll
        for (int j = 0; j < 4; ++j) acc[i][j] = 0ull;

    float4 a0 = *(const float4*)(Aptr);
    float4 a1 = *(const float4*)(Aptr + 64 * NDIM);
    float4 b0 = *(const float4*)(Bptr);
    float4 b1 = *(const float4*)(Bptr + 8 * G3);

    for (int kc = 0; kc < NDIM; kc += KB1) {
        As[ac0 + 0][ar0] = a0.x; As[ac0 + 1][ar0] = a0.y;
        As[ac0 + 2][ar0] = a0.z; As[ac0 + 3][ar0] = a0.w;
        As[ac0 + 0][ar0 + 64] = a1.x; As[ac0 + 1][ar0 + 64] = a1.y;
        As[ac0 + 2][ar0 + 64] = a1.z; As[ac0 + 3][ar0 + 64] = a1.w;
        *(float4*)&Bs[bk0][bn0]     = b0;
        *(float4*)&Bs[bk0 + 8][bn0] = b1;
        __syncthreads();

        if (kc + KB1 < NDIM) {
            a0 = *(const float4*)(Aptr + (kc + KB1));
            a1 = *(const float4*)(Aptr + (kc + KB1) + 64 * NDIM);
            b0 = *(const float4*)(Bptr + (size_t)(kc + KB1) * G3);
            b1 = *(const float4*)(Bptr + (size_t)(kc + KB1 + 8) * G3);
        }

#pragma unroll
        for (int kk = 0; kk < KB1; ++kk) {
            float4 aA = *(const float4*)&As[kk][tm * 8];
            float4 aB = *(const float4*)&As[kk][tm * 8 + 4];
            u64 bp0 = *(const u64*)&Bs[kk][tn * 8 + 0];
            u64 bp1 = *(const u64*)&Bs[kk][tn * 8 + 2];
            u64 bp2 = *(const u64*)&Bs[kk][tn * 8 + 4];
            u64 bp3 = *(const u64*)&Bs[kk][tn * 8 + 6];
            u64 ad[8];
            ad[0] = pk2(aA.x, aA.x); ad[1] = pk2(aA.y, aA.y);
            ad[2] = pk2(aA.z, aA.z); ad[3] = pk2(aA.w, aA.w);
            ad[4] = pk2(aB.x, aB.x); ad[5] = pk2(aB.y, aB.y);
            ad[6] = pk2(aB.z, aB.z); ad[7] = pk2(aB.w, aB.w);
#pragma unroll
            for (int i = 0; i < 8; ++i) {
                acc[i][0] = ffma2(ad[i], bp0, acc[i][0]);
                acc[i][1] = ffma2(ad[i], bp1, acc[i][1]);
                acc[i][2] = ffma2(ad[i], bp2, acc[i][2]);
                acc[i][3] = ffma2(ad[i], bp3, acc[i][3]);
            }
        }
        __syncthreads();
    }

    float bb[8];
#pragma unroll
    for (int j = 0; j < 8; ++j) bb[j] = __ldg(bias + nBase + tn * 8 + j);

#pragma unroll
    for (int i = 0; i < 8; ++i) {
        size_t row = (size_t)(mBase + tm * 8 + i);
        float* o = g_gx + row * G3 + nBase + tn * 8;
        float2 p0 = up2(acc[i][0]), p1 = up2(acc[i][1]);
        float2 p2 = up2(acc[i][2]), p3 = up2(acc[i][3]);
        float4 lo = make_float4(p0.x + bb[0], p0.y + bb[1], p1.x + bb[2], p1.y + bb[3]);
        float4 hi = make_float4(p2.x + bb[4], p2.y + bb[5], p3.x + bb[6], p3.y + bb[7]);
        *(float4*)(o)     = lo;
        *(float4*)(o + 4) = hi;
    }
}

// =====================================================================
// Phase 2: GRU recurrence. 16 clusters x 8 CTAs; cluster = 8 batches;
// CTA = 32 hidden columns. 512 threads (16-way k-split).
// Reduce/broadcast threads remapped (lb=tid&7, hc=tid>>3) so the
// h-broadcast st.async is fully coalesced (slot = rank*256 + tid).
// Smem: Ws[256][32][4] 128KB | hbuf[2][256][8] 16KB | part[16*8][100] 50KB | mbar[2]
// =====================================================================
#define WS_FLOATS   (256 * 32 * 4)          // 32768
#define HB_FLOATS   (2 * 256 * 8)           // 4096
#define PART_STRIDE 100                     // 3*32 + 4 pad (bank spread)
#define PART_FLOATS (16 * 8 * PART_STRIDE)  // 12800
#define HB_OFF_B    (WS_FLOATS * 4)                               // 131072
#define BAR_OFF_B   ((WS_FLOATS + HB_FLOATS + PART_FLOATS) * 4)   // 198656
#define SMEM2_BYTES (BAR_OFF_B + 16)
#define TX_BYTES    8192u                   // 8 CTAs x 256 floats x 4B per step

__global__ void __launch_bounds__(512, 1) __cluster_dims__(8, 1, 1)
gru_rec(const float* __restrict__ mask, const float* __restrict__ Whh,
        const float* __restrict__ bhh, float* __restrict__ out)
{
    extern __shared__ float smem[];
    float* Ws   = smem;                          // [k][hc][4]
    float* hbuf = smem + WS_FLOATS;              // [buf][k][lb]  (k = global h index)
    float* part = smem + WS_FLOATS + HB_FLOATS;  // [(ks*8+lb)*100 + g*32 + hc]

    const int tid  = threadIdx.x;
    const int rank = blockIdx.x & 7;
    const int cid  = blockIdx.x >> 3;
    const int hc   = tid & 31;                  // k-loop lane role
    const int ks   = tid >> 5;                  // 0..15 (k-split warp)
    // reduce-phase remap (tid < 256): lb fast, hc slow -> coalesced broadcast
    const int rlb  = tid & 7;
    const int rhc  = (tid >> 3) & 31;
    const int rhcg = rank * 32 + rhc;

    // ---- load W_hh slice: Ws[k][hc][g] = Whh[k][g*256 + (rank*32+hc)] ----
    for (int idx = tid; idx < 256 * 32 * 3; idx += 512) {
        int g  = idx >> 13;
        int r  = idx & 8191;
        int k  = r >> 5;
        int h2 = r & 31;
        Ws[k * 128 + h2 * 4 + g] = __ldg(Whh + (size_t)k * G3 + g * 256 + rank * 32 + h2);
    }
    for (int idx = tid; idx < HB_FLOATS; idx += 512) hbuf[idx] = 0.f;

    const unsigned smem_base = smem_u32(smem);
    const unsigned barL0 = smem_base + BAR_OFF_B;
    const unsigned barL1 = smem_base + BAR_OFF_B + 8;
    if (tid == 0) {
        mbar_init(barL0, 1);
        mbar_init(barL1, 1);
        mbar_expect_tx(barL0, TX_BYTES);
        mbar_expect_tx(barL1, TX_BYTES);
    }

    const float bhr = __ldg(bhh + 0 * 256 + rhcg);
    const float bhz = __ldg(bhh + 1 * 256 + rhcg);
    const float bhn = __ldg(bhh + 2 * 256 + rhcg);

    // remote smem bases for all 8 cluster ranks
    unsigned rbase[8];
#pragma unroll
    for (int r = 0; r < 8; ++r) rbase[r] = mapa_rank(smem_base, r);
    // this thread's h slot (same offset in every rank's hbuf): rank*256 + tid
    const unsigned slot_off = (unsigned)((rank * 256 + tid) * 4);

    const int b_glob = cid * 8 + rlb;
    size_t gxbase = (size_t)b_glob * NS * G3 + rhcg;
    size_t obase  = (size_t)b_glob * NS * NH + rhcg;
    size_t mbase  = (size_t)b_glob * NS;

    const float* wp = Ws + ks * 16 * 128 + hc * 4;   // this warp's k-range
    __syncthreads();
    CLUSTER_SYNC();   // barriers + zeroed hbuf visible cluster-wide

    unsigned p0 = 0, p1 = 0;   // per-buffer wait parity

    for (int t = 0; t < NS; ++t) {
        const int cur = t & 1;

        // prefetch gx + mask BEFORE the wait (independent of h)
        float gxr = 0.f, gxz = 0.f, gxn = 0.f, mv = 0.f;
        if (tid < 256) {
            gxr = __ldg(g_gx + gxbase + 0);
            gxz = __ldg(g_gx + gxbase + 256);
            gxn = __ldg(g_gx + gxbase + 512);
            mv  = __ldg(mask + mbase + t);
        }

        if (t > 0) {
            if (cur == 0) { mbar_wait(barL0, p0); p0 ^= 1; }
            else          { mbar_wait(barL1, p1); p1 ^= 1; }
            if (tid == 0 && t + 2 < NS)
                mbar_expect_tx(cur ? barL1 : barL0, TX_BYTES);
        }

        // ---- gh partial: 16 k x 8 batches x 3 gates per thread ----
        const float* hp = hbuf + cur * 2048 + ks * 128;
        u64 ar0 = 0, ar1 = 0, ar2 = 0, ar3 = 0;
        u64 az0 = 0, az1 = 0, az2 = 0, az3 = 0;
        u64 an0 = 0, an1 = 0, an2 = 0, an3 = 0;
#pragma unroll
        for (int kk = 0; kk < 16; ++kk) {
            float4 w = *(const float4*)(wp + kk * 128);
            ulonglong2 q0 = *(const ulonglong2*)(hp + kk * 8);
            ulonglong2 q1 = *(const ulonglong2*)(hp + kk * 8 + 4);
            u64 wr = pk2(w.x, w.x), wz = pk2(w.y, w.y), wn = pk2(w.z, w.z);
            ar0 = ffma2(wr, q0.x, ar0); ar1 = ffma2(wr, q0.y, ar1);
            ar2 = ffma2(wr, q1.x, ar2); ar3 = ffma2(wr, q1.y, ar3);
            az0 = ffma2(wz, q0.x, az0); az1 = ffma2(wz, q0.y, az1);
            az2 = ffma2(wz, q1.x, az2); az3 = ffma2(wz, q1.y, az3);
            an0 = ffma2(wn, q0.x, an0); an1 = ffma2(wn, q0.y, an1);
            an2 = ffma2(wn, q1.x, an2); an3 = ffma2(wn, q1.y, an3);
        }
        {
            float2 v;
            float* pb = part + ks * 8 * PART_STRIDE + hc;
#define PW(G, LB0, V0, V1) \
            pb[(LB0) * PART_STRIDE + (G) * 32] = (V0); \
            pb[((LB0) + 1) * PART_STRIDE + (G) * 32] = (V1);
            v = up2(ar0); PW(0, 0, v.x, v.y)
            v = up2(ar1); PW(0, 2, v.x, v.y)
            v = up2(ar2); PW(0, 4, v.x, v.y)
            v = up2(ar3); PW(0, 6, v.x, v.y)
            v = up2(az0); PW(1, 0, v.x, v.y)
            v = up2(az1); PW(1, 2, v.x, v.y)
            v = up2(az2); PW(1, 4, v.x, v.y)
            v = up2(az3); PW(1, 6, v.x, v.y)
            v = up2(an0); PW(2, 0, v.x, v.y)
            v = up2(an1); PW(2, 2, v.x, v.y)
            v = up2(an2); PW(2, 4, v.x, v.y)
            v = up2(an3); PW(2, 6, v.x, v.y)
#undef PW
        }

        // split barrier: producer-only warps arrive and move on; reducers sync.
        if (tid < 256) {
            asm volatile("bar.sync 1, 512;" ::: "memory");

            // ---- reduce over 16 k-splits; thread = (rlb, rhc) ----
            float sr = 0.f, sz = 0.f, sn = 0.f;
#pragma unroll
            for (int k2 = 0; k2 < 16; ++k2) {
                const float* pp = part + (k2 * 8 + rlb) * PART_STRIDE + rhc;
                sr += pp[0]; sz += pp[32]; sn += pp[64];
            }
            const float ghr = sr + bhr;
            const float ghz = sz + bhz;
            const float ghn = sn + bhn;
            const float r = sigm_fast(gxr + ghr);
            const float z = sigm_fast(gxz + ghz);
            const float n = tanh_fast(gxn + r * ghn);
            const float hprev = hbuf[cur * 2048 + rank * 256 + tid];
            const float hnew  = (1.f - z) * n + z * hprev;
            const float ho    = mv * hnew + (1.f - mv) * hprev;

            // broadcast first (critical path), then global store
            if (t + 1 < NS) {
                const int nxt = cur ^ 1;
                const unsigned c_data = HB_OFF_B + (unsigned)nxt * 8192u + slot_off;
                const unsigned c_bar  = BAR_OFF_B + (unsigned)nxt * 8u;
                const unsigned hv = __float_as_uint(ho);
#pragma unroll
                for (int r2 = 0; r2 < 8; ++r2)
                    st_async_tx(rbase[r2] + c_data, hv, rbase[r2] + c_bar);
            }
            out[obase] = ho;
        } else {
            asm volatile("bar.arrive 1, 512;" ::: "memory");
        }

        gxbase += G3;
        obase  += NH;
    }
}

extern "C" void kernel_launch(void* const* d_in, const int* in_sizes, int n_in,
                              void* d_out, int out_size) {
    const float* x    = (const float*)d_in[0];   // [B,S,D]
    const float* mask = (const float*)d_in[1];   // [B,S]
    const float* Wih  = (const float*)d_in[2];   // [D,3H]
    const float* Whh  = (const float*)d_in[3];   // [H,3H]
    const float* bih  = (const float*)d_in[4];   // [3H]
    const float* bhh  = (const float*)d_in[5];   // [3H]
    float* out = (float*)d_out;                  // [B,S,H]

    (void)in_sizes; (void)n_in; (void)out_size;

    // Phase 1: input projection GEMM
    dim3 g1(G3 / 128, (NB * NS) / 128);          // (6, 1024)
    gru_gemm1<<<g1, 256>>>(x, Wih, bih);

    // Phase 2: clustered recurrence
    cudaFuncSetAttribute(gru_rec, cudaFuncAttributeMaxDynamicSharedMemorySize,
                         SMEM2_BYTES);
    gru_rec<<<128, 512, SMEM2_BYTES>>>(mask, Whh, bhh, out);
}